// round 14
// baseline (speedup 1.0000x reference)
#include <cuda_runtime.h>
#include <cuda_fp16.h>
#include <cstdint>
#include <cstddef>

// Problem constants
#define BB 2
#define SS 2048
#define DD 1024
#define HH 16
#define DH 64
#define MROWS (BB*SS)          // 4096
#define D4 (4*DD)              // 4096
#define WSEG 1048576           // 1M elements per D*D weight
#define GEMM_GRID 296          // 2 CTA/SM x 148 SMs (persistent tiles)

// ---------------- scratch (device globals; no allocations) ----------------
__device__ __half g_wh [10*WSEG];     // wq | fc | w1 | w2 (fp16)
__device__ __half g_xh [MROWS*DD];    // x fp16
__device__ __half g_qh [MROWS*DD];    // q projection fp16
__device__ __half g_ah [MROWS*DD];    // attention out fp16
__device__ __half g_l1h[MROWS*DD];    // ln1 fp16
__device__ __half g_hh [MROWS*D4];    // mlp hidden fp16 (relu'd)
__device__ float  g_t1 [MROWS*DD];
__device__ float  g_t2 [MROWS*DD];

// ================= helpers =================
__device__ __forceinline__ uint32_t smem_u32(const void* p) {
    uint32_t a;
    asm("{ .reg .u64 t; cvta.to.shared.u64 t, %1; cvt.u32.u64 %0, t; }" : "=r"(a) : "l"(p));
    return a;
}
__device__ __forceinline__ float ex2(float x) {
    float y; asm("ex2.approx.ftz.f32 %0, %1;" : "=f"(y) : "f"(x)); return y;
}
__device__ __forceinline__ uint32_t cvth2(float x, float y) {
    uint32_t h;
    asm("cvt.rn.f16x2.f32 %0, %1, %2;" : "=r"(h) : "f"(y), "f"(x));
    return h;
}
__device__ __forceinline__ void ldsm4(uint32_t* r, uint32_t addr) {
    asm volatile("ldmatrix.sync.aligned.m8n8.x4.shared.b16 {%0,%1,%2,%3}, [%4];"
                 : "=r"(r[0]), "=r"(r[1]), "=r"(r[2]), "=r"(r[3]) : "r"(addr));
}
__device__ __forceinline__ void ldsm4t(uint32_t* r, uint32_t addr) {
    asm volatile("ldmatrix.sync.aligned.m8n8.x4.trans.shared.b16 {%0,%1,%2,%3}, [%4];"
                 : "=r"(r[0]), "=r"(r[1]), "=r"(r[2]), "=r"(r[3]) : "r"(addr));
}
__device__ __forceinline__ void mma16816(float* d, const uint32_t* a, uint32_t b0, uint32_t b1) {
    asm volatile(
        "mma.sync.aligned.m16n8k16.row.col.f32.f16.f16.f32 "
        "{%0,%1,%2,%3}, {%4,%5,%6,%7}, {%8,%9}, {%0,%1,%2,%3};"
        : "+f"(d[0]), "+f"(d[1]), "+f"(d[2]), "+f"(d[3])
        : "r"(a[0]), "r"(a[1]), "r"(a[2]), "r"(a[3]), "r"(b0), "r"(b1));
}
__device__ __forceinline__ void cp16(uint32_t dst, const void* src) {
    asm volatile("cp.async.cg.shared.global [%0], [%1], 16;" :: "r"(dst), "l"(src) : "memory");
}
#define CP_COMMIT() asm volatile("cp.async.commit_group;" ::: "memory")
#define CP_WAIT0()  asm volatile("cp.async.wait_group 0;" ::: "memory")
#define CP_WAIT1()  asm volatile("cp.async.wait_group 1;" ::: "memory")
#define CP_WAIT2()  asm volatile("cp.async.wait_group 2;" ::: "memory")

// ================= pack wq_w [H,D,Dh] -> Wq fp16 [D, D] =================
__global__ void pack_wq_kernel(const float* __restrict__ wq_w, __half* __restrict__ Wq) {
    int idx = blockIdx.x * blockDim.x + threadIdx.x;
    if (idx >= DD * DD) return;
    int d = idx / DD;
    int n = idx % DD;
    int h = n / DH;
    int e = n % DH;
    Wq[idx] = __float2half_rn(wq_w[((size_t)h * DD + d) * DH + e]);
}

// ================= fp32 -> fp16 converter (simple, one float4/thread) =================
__global__ void conv_f16_kernel(const float* __restrict__ src, __half* __restrict__ dst, int n4) {
    int i = blockIdx.x * blockDim.x + threadIdx.x;
    if (i >= n4) return;
    float4 v = ((const float4*)src)[i];
    uint2 o;
    o.x = cvth2(v.x, v.y);
    o.y = cvth2(v.z, v.w);
    ((uint2*)dst)[i] = o;
}

// ================= fp16 HMMA GEMM (persistent tiles, 256 thr, warp 64x32, K-stage 64) =
// Residual can be fp32 (resid) or fp16 (residh).
#define STAGE_BYTES 32768
#define HMMA_SMEM (3 * STAGE_BYTES + 128)

__global__ __launch_bounds__(256, 2) void hmma_gemm_kernel(
    const __half* __restrict__ A, const __half* __restrict__ W,
    const float* __restrict__ bias,
    const float* __restrict__ resid, const __half* __restrict__ residh,
    float* __restrict__ C, __half* __restrict__ Ch,
    int M, int N, int K, int relu)
{
    extern __shared__ char dsm_raw[];
    uint32_t sraw = smem_u32(dsm_raw);
    uint32_t sb = (sraw + 127u) & ~127u;

    const int tid = threadIdx.x;
    const int wid = tid >> 5;
    const int l   = tid & 31;
    const int wm  = wid >> 2;     // 0..1
    const int wn  = wid & 3;      // 0..3

    const int ntx = N >> 7;
    const int ntiles = (M >> 7) * ntx;
    const int NS = K >> 6;   // K-stage 64

    const uint32_t l15 = l & 15;
    const uint32_t ack = (uint32_t)(l >> 4);
    const uint32_t bk7 = (uint32_t)(l & 7);
    const uint32_t bka = (uint32_t)(l >> 4) * 8;
    const uint32_t bna = (uint32_t)((l >> 3) & 1) * 8;

    for (int t = blockIdx.x; t < ntiles; t += gridDim.x) {
        const int row0 = (t / ntx) << 7;
        const int col0 = (t % ntx) << 7;

        float acc[16][4];
#pragma unroll
        for (int i = 0; i < 16; i++)
#pragma unroll
            for (int j = 0; j < 4; j++) acc[i][j] = 0.f;

        auto cpStage = [&](int s) {
            uint32_t base = sb + (uint32_t)(s % 3) * STAGE_BYTES;
            int k0 = s << 6;
#pragma unroll
            for (int i = 0; i < 4; i++) {
                int idx = tid + i * 256;
                uint32_t r = (uint32_t)idx >> 3, c = (uint32_t)idx & 7;
                uint32_t aoff = r * 128 + ((c ^ (r & 7)) << 4);
                cp16(base + aoff, A + (size_t)(row0 + r) * K + k0 + c * 8);
            }
#pragma unroll
            for (int i = 0; i < 4; i++) {
                int idx = tid + i * 256;
                uint32_t k = (uint32_t)idx >> 4, c = (uint32_t)idx & 15;
                uint32_t boff = k * 256 + ((c ^ (k & 7)) << 4);
                cp16(base + 16384 + boff, W + (size_t)(k0 + k) * N + col0 + c * 8);
            }
            CP_COMMIT();
        };

        cpStage(0);
        if (NS > 1) cpStage(1);

        for (int s = 0; s < NS; s++) {
            __syncthreads();
            if (s + 2 < NS) { cpStage(s + 2); CP_WAIT2(); }
            else if (s + 1 < NS) { CP_WAIT1(); }
            else { CP_WAIT0(); }
            __syncthreads();

            uint32_t base = sb + (uint32_t)(s % 3) * STAGE_BYTES;
            uint32_t Ab = base, Bb = base + 16384;

#pragma unroll
            for (int kk16 = 0; kk16 < 4; kk16++) {
                uint32_t ah[4][4], bh[2][4];
                uint32_t ac = (uint32_t)(kk16 * 2) + ack;
#pragma unroll
                for (int i = 0; i < 4; i++) {
                    uint32_t row = wm * 64 + i * 16 + l15;
                    uint32_t ad = row * 128 + ((ac ^ (row & 7)) << 4);
                    ldsm4(ah[i], Ab + ad);
                }
#pragma unroll
                for (int j2 = 0; j2 < 2; j2++) {
                    uint32_t krow = (uint32_t)(kk16 * 16) + bka + bk7;
                    uint32_t ncol = wn * 32 + j2 * 16 + bna;
                    uint32_t bd = krow * 256 + (((ncol >> 3) ^ bk7) << 4);
                    ldsm4t(bh[j2], Bb + bd);
                }
#pragma unroll
                for (int i = 0; i < 4; i++) {
#pragma unroll
                    for (int j = 0; j < 4; j++) {
                        int j2 = j >> 1, jj = j & 1;
                        mma16816(acc[i * 4 + j], ah[i], bh[j2][jj], bh[j2][2 + jj]);
                    }
                }
            }
        }

        // ---- epilogue ----
        const int tq = l >> 2;
        const int tr = (l & 3) * 2;
#pragma unroll
        for (int j = 0; j < 4; j++) {
            int c = col0 + wn * 32 + j * 8 + tr;
            float bx = 0.f, by = 0.f;
            if (bias) { bx = bias[c]; by = bias[c + 1]; }
#pragma unroll
            for (int i = 0; i < 4; i++) {
                int m0 = row0 + wm * 64 + i * 16 + tq;
                float* d = acc[i * 4 + j];
                float v0x = d[0] + bx, v0y = d[1] + by;
                float v1x = d[2] + bx, v1y = d[3] + by;
                if (relu) {
                    v0x = fmaxf(v0x, 0.f); v0y = fmaxf(v0y, 0.f);
                    v1x = fmaxf(v1x, 0.f); v1y = fmaxf(v1y, 0.f);
                }
                if (Ch) {
                    *(uint32_t*)((uint16_t*)Ch + (size_t)m0 * N + c) = cvth2(v0x, v0y);
                    *(uint32_t*)((uint16_t*)Ch + (size_t)(m0 + 8) * N + c) = cvth2(v1x, v1y);
                } else {
                    if (resid) {
                        float2 r0 = *(const float2*)(resid + (size_t)m0 * N + c);
                        float2 r1 = *(const float2*)(resid + (size_t)(m0 + 8) * N + c);
                        v0x += r0.x; v0y += r0.y; v1x += r1.x; v1y += r1.y;
                    } else if (residh) {
                        __half2 h0 = *(const __half2*)(residh + (size_t)m0 * N + c);
                        __half2 h1 = *(const __half2*)(residh + (size_t)(m0 + 8) * N + c);
                        float2 r0 = __half22float2(h0);
                        float2 r1 = __half22float2(h1);
                        v0x += r0.x; v0y += r0.y; v1x += r1.x; v1y += r1.y;
                    }
                    *(float2*)(C + (size_t)m0 * N + c) = make_float2(v0x, v0y);
                    *(float2*)(C + (size_t)(m0 + 8) * N + c) = make_float2(v1x, v1y);
                }
            }
        }
        __syncthreads();   // protect stage buffers before next tile's cpStage(0)
    }
}

// ================= flash attention, fp16 HMMA (Q=K=V), q-tile 64 (R11 config) =========
#define FLASH_SMEM (40 * 1024 + 128)
#define SCALE2 0.18033688011112042f   /* log2(e)/8 */

__global__ __launch_bounds__(128, 3) void flash_hmma_kernel(
    const __half* __restrict__ qh, __half* __restrict__ oh)
{
    extern __shared__ char dsm_raw[];
    uint32_t sraw = smem_u32(dsm_raw);
    uint32_t sb = (sraw + 127u) & ~127u;

    const int tid = threadIdx.x;
    const int w   = tid >> 5;
    const int l   = tid & 31;
    const int q0  = blockIdx.x * 64;
    const int h   = blockIdx.y;
    const int b   = blockIdx.z;

    const uint32_t Qb = sb;
    const size_t gbase = (size_t)b * SS * DD + h * DH;

    {
#pragma unroll
        for (int i = 0; i < 4; i++) {
            int idx = tid + i * 128;
            uint32_t r = idx >> 3, c = idx & 7;
            uint32_t off = r * 128 + ((c ^ (r & 7)) << 4);
            cp16(Qb + off, qh + gbase + (size_t)(q0 + r) * DD + c * 8);
        }
#pragma unroll
        for (int i = 0; i < 8; i++) {
            int idx = tid + i * 128;
            uint32_t r = idx >> 3, c = idx & 7;
            uint32_t off = r * 128 + ((c ^ (r & 7)) << 4);
            cp16(sb + 8192 + off, qh + gbase + (size_t)r * DD + c * 8);
        }
        CP_COMMIT();
    }

    uint32_t aq[4][4];
    float S[16][4];
    float O[8][4];
    float m0 = -1e30f, m1 = -1e30f, l0 = 0.f, l1 = 0.f;
#pragma unroll
    for (int i = 0; i < 8; i++)
#pragma unroll
        for (int j = 0; j < 4; j++) O[i][j] = 0.f;

    const uint32_t l15 = l & 15;
    const uint32_t keyoff = (uint32_t)((l & 7) + ((l >> 3) & 1) * 8);
    const uint32_t kcadd  = (uint32_t)(l >> 4);
    const uint32_t vk7    = (uint32_t)(l & 7);
    const uint32_t vka    = (uint32_t)(l >> 4) * 8;
    const uint32_t vna    = (uint32_t)((l >> 3) & 1);

    const int NT = SS / 128;
    for (int kt = 0; kt < NT; kt++) {
        int p = kt & 1;
        __syncthreads();
        if (kt + 1 < NT) {
            uint32_t Kd = sb + 8192 + (uint32_t)(p ^ 1) * 16384u;
#pragma unroll
            for (int i = 0; i < 8; i++) {
                int idx = tid + i * 128;
                uint32_t r = idx >> 3, c = idx & 7;
                uint32_t off = r * 128 + ((c ^ (r & 7)) << 4);
                cp16(Kd + off, qh + gbase + (size_t)((kt + 1) * 128 + r) * DD + c * 8);
            }
            CP_COMMIT();
            CP_WAIT1();
        } else {
            CP_WAIT0();
        }
        __syncthreads();

        if (kt == 0) {
#pragma unroll
            for (int ks = 0; ks < 4; ks++) {
                uint32_t row = (uint32_t)(w * 16) + l15;
                uint32_t ch = (uint32_t)(ks * 2) + kcadd;
                uint32_t ad = row * 128 + ((ch ^ (row & 7)) << 4);
                ldsm4(aq[ks], Qb + ad);
            }
        }

        uint32_t Kb = sb + 8192 + (uint32_t)p * 16384u;

        // ---- S = Q @ K^T ----
#pragma unroll
        for (int nt = 0; nt < 16; nt++)
#pragma unroll
            for (int c = 0; c < 4; c++) S[nt][c] = 0.f;
#pragma unroll
        for (int ks = 0; ks < 4; ks++) {
#pragma unroll
            for (int nb = 0; nb < 8; nb++) {
                uint32_t key = (uint32_t)(nb * 16) + keyoff;
                uint32_t ch = (uint32_t)(ks * 2) + kcadd;
                uint32_t ad = key * 128 + ((ch ^ (key & 7)) << 4);
                uint32_t bh[4];
                ldsm4(bh, Kb + ad);
#pragma unroll
                for (int jj = 0; jj < 2; jj++)
                    mma16816(S[nb * 2 + jj], aq[ks], bh[jj], bh[2 + jj]);
            }
        }

        // ---- online softmax ----
        float mx0 = -1e30f, mx1 = -1e30f;
#pragma unroll
        for (int nt = 0; nt < 16; nt++) {
            mx0 = fmaxf(mx0, fmaxf(S[nt][0], S[nt][1]));
            mx1 = fmaxf(mx1, fmaxf(S[nt][2], S[nt][3]));
        }
        mx0 = fmaxf(mx0, __shfl_xor_sync(0xffffffffu, mx0, 1));
        mx0 = fmaxf(mx0, __shfl_xor_sync(0xffffffffu, mx0, 2));
        mx1 = fmaxf(mx1, __shfl_xor_sync(0xffffffffu, mx1, 1));
        mx1 = fmaxf(mx1, __shfl_xor_sync(0xffffffffu, mx1, 2));
        float mn0 = fmaxf(m0, mx0), mn1 = fmaxf(m1, mx1);
        float s0 = 0.f, s1 = 0.f;
#pragma unroll
        for (int nt = 0; nt < 16; nt++) {
            S[nt][0] = ex2((S[nt][0] - mn0) * SCALE2);
            S[nt][1] = ex2((S[nt][1] - mn0) * SCALE2);
            S[nt][2] = ex2((S[nt][2] - mn1) * SCALE2);
            S[nt][3] = ex2((S[nt][3] - mn1) * SCALE2);
            s0 += S[nt][0] + S[nt][1];
            s1 += S[nt][2] + S[nt][3];
        }
        s0 += __shfl_xor_sync(0xffffffffu, s0, 1);
        s0 += __shfl_xor_sync(0xffffffffu, s0, 2);
        s1 += __shfl_xor_sync(0xffffffffu, s1, 1);
        s1 += __shfl_xor_sync(0xffffffffu, s1, 2);
        float a0 = ex2((m0 - mn0) * SCALE2);
        float a1 = ex2((m1 - mn1) * SCALE2);
        l0 = l0 * a0 + s0;
        l1 = l1 * a1 + s1;
        m0 = mn0; m1 = mn1;
#pragma unroll
        for (int nt = 0; nt < 8; nt++) {
            O[nt][0] *= a0; O[nt][1] *= a0;
            O[nt][2] *= a1; O[nt][3] *= a1;
        }

        // ---- O += P @ V ----
#pragma unroll
        for (int kp = 0; kp < 8; kp++) {
            uint32_t ph[4];
            ph[0] = cvth2(S[2 * kp][0],     S[2 * kp][1]);
            ph[1] = cvth2(S[2 * kp][2],     S[2 * kp][3]);
            ph[2] = cvth2(S[2 * kp + 1][0], S[2 * kp + 1][1]);
            ph[3] = cvth2(S[2 * kp + 1][2], S[2 * kp + 1][3]);
#pragma unroll
            for (int j2 = 0; j2 < 4; j2++) {
                uint32_t krow = (uint32_t)(kp * 16) + vka + vk7;
                uint32_t chn = (uint32_t)(j2 * 2) + vna;
                uint32_t ad = krow * 128 + ((chn ^ (krow & 7)) << 4);
                uint32_t vh[4];
                ldsm4t(vh, Kb + ad);
#pragma unroll
                for (int jj = 0; jj < 2; jj++)
                    mma16816(O[j2 * 2 + jj], ph, vh[jj], vh[2 + jj]);
            }
        }
    }

    // ---- write normalized output as fp16 ----
    float inv0 = 1.0f / l0, inv1 = 1.0f / l1;
    int r0 = l >> 2;
    int fb = (l & 3) * 2;
    uint16_t* op = (uint16_t*)oh + gbase + (size_t)(q0 + w * 16) * DD;
#pragma unroll
    for (int nt = 0; nt < 8; nt++) {
        int f = nt * 8 + fb;
        *(uint32_t*)(op + (size_t)r0 * DD + f) = cvth2(O[nt][0] * inv0, O[nt][1] * inv0);
        *(uint32_t*)(op + (size_t)(r0 + 8) * DD + f) = cvth2(O[nt][2] * inv1, O[nt][3] * inv1);
    }
}

// ================= layernorm: warp-per-row; fp32 out and/or fp16 out optional =========
__global__ __launch_bounds__(256) void ln_kernel(
    const float* __restrict__ in, const float* __restrict__ gw,
    const float* __restrict__ bw, float* __restrict__ out,
    __half* __restrict__ oh)
{
    const int warp = threadIdx.x >> 5;
    const int lane = threadIdx.x & 31;
    const int row = blockIdx.x * 8 + warp;

    const float4* p = (const float4*)(in + (size_t)row * DD);
    float4 v[8];
#pragma unroll
    for (int i = 0; i < 8; i++) v[i] = p[lane + i * 32];

    float s = 0.f, sq = 0.f;
#pragma unroll
    for (int i = 0; i < 8; i++) {
        s  += v[i].x + v[i].y + v[i].z + v[i].w;
        sq += v[i].x * v[i].x + v[i].y * v[i].y + v[i].z * v[i].z + v[i].w * v[i].w;
    }
#pragma unroll
    for (int off = 16; off > 0; off >>= 1) {
        s  += __shfl_xor_sync(0xffffffffu, s,  off);
        sq += __shfl_xor_sync(0xffffffffu, sq, off);
    }
    const float mu  = s * (1.0f / DD);
    const float var = sq * (1.0f / DD) - mu * mu;
    const float r   = rsqrtf(var + 1e-5f);

    float4* po = out ? (float4*)(out + (size_t)row * DD) : nullptr;
    uint2* ph = oh ? (uint2*)oh + (size_t)row * (DD / 4) : nullptr;
#pragma unroll
    for (int i = 0; i < 8; i++) {
        int c = lane + i * 32;
        const float4 g4 = ((const float4*)gw)[c];
        const float4 b4 = ((const float4*)bw)[c];
        float4 ov;
        ov.x = (v[i].x - mu) * r * g4.x + b4.x;
        ov.y = (v[i].y - mu) * r * g4.y + b4.y;
        ov.z = (v[i].z - mu) * r * g4.z + b4.z;
        ov.w = (v[i].w - mu) * r * g4.w + b4.w;
        if (po) po[c] = ov;
        if (ph) {
            uint2 o;
            o.x = cvth2(ov.x, ov.y);
            o.y = cvth2(ov.z, ov.w);
            ph[c] = o;
        }
    }
}

// ================= launch =================
extern "C" void kernel_launch(void* const* d_in, const int* in_sizes, int n_in,
                              void* d_out, int out_size)
{
    const float* x     = (const float*)d_in[0];
    const float* wq_w  = (const float*)d_in[1];
    const float* wq_b  = (const float*)d_in[2];
    const float* fc_w  = (const float*)d_in[3];
    const float* fc_b  = (const float*)d_in[4];
    const float* ln1_g = (const float*)d_in[5];
    const float* ln1_b = (const float*)d_in[6];
    const float* w1    = (const float*)d_in[7];
    const float* b1    = (const float*)d_in[8];
    const float* w2    = (const float*)d_in[9];
    const float* b2    = (const float*)d_in[10];
    const float* ln2_g = (const float*)d_in[11];
    const float* ln2_b = (const float*)d_in[12];
    float* out = (float*)d_out;

    float *t1, *t2;
    __half *wh, *xh, *qh, *ah, *l1h, *hh;
    cudaGetSymbolAddress((void**)&wh,  g_wh);
    cudaGetSymbolAddress((void**)&xh,  g_xh);
    cudaGetSymbolAddress((void**)&qh,  g_qh);
    cudaGetSymbolAddress((void**)&ah,  g_ah);
    cudaGetSymbolAddress((void**)&l1h, g_l1h);
    cudaGetSymbolAddress((void**)&hh,  g_hh);
    cudaGetSymbolAddress((void**)&t1,  g_t1);
    cudaGetSymbolAddress((void**)&t2,  g_t2);

    cudaFuncSetAttribute(hmma_gemm_kernel, cudaFuncAttributeMaxDynamicSharedMemorySize, HMMA_SMEM);
    cudaFuncSetAttribute(flash_hmma_kernel, cudaFuncAttributeMaxDynamicSharedMemorySize, FLASH_SMEM);

    // 1) pack Wq (fp16); convert weights + x to fp16
    pack_wq_kernel<<<(DD * DD + 255) / 256, 256>>>(wq_w, wh);
    conv_f16_kernel<<<(WSEG / 4 + 255) / 256, 256>>>(fc_w, wh + WSEG, WSEG / 4);
    conv_f16_kernel<<<(WSEG + 255) / 256, 256>>>(w1, wh + 2 * WSEG, WSEG);
    conv_f16_kernel<<<(WSEG + 255) / 256, 256>>>(w2, wh + 6 * WSEG, WSEG);
    conv_f16_kernel<<<(MROWS * DD / 4 + 255) / 256, 256>>>(x, xh, MROWS * DD / 4);

    // 2) qh = x @ Wq + wq_b  (fp16 out)  [256 tiles]
    hmma_gemm_kernel<<<256, 256, HMMA_SMEM>>>(
        xh, wh, wq_b, nullptr, nullptr, nullptr, qh, MROWS, DD, DD, 0);
    // 3) flash attention (fp16 out), q-tile 64, 3 CTA/SM
    flash_hmma_kernel<<<dim3(SS / 64, HH, BB), 128, FLASH_SMEM>>>(qh, ah);
    // 4) t1 = attn @ fc_w + fc_b + xh (fp16 residual) -> fp32  [256 tiles]
    hmma_gemm_kernel<<<256, 256, HMMA_SMEM>>>(
        ah, wh + WSEG, fc_b, nullptr, xh, t1, nullptr, MROWS, DD, DD, 0);
    // 5) ln1 = LN(t1) -> fp16 only
    ln_kernel<<<MROWS / 8, 256>>>(t1, ln1_g, ln1_b, nullptr, l1h);
    // 6) h = relu(ln1 @ w1 + b1) (fp16 out)  [1024 tiles -> persistent 296]
    hmma_gemm_kernel<<<GEMM_GRID, 256, HMMA_SMEM>>>(
        l1h, wh + 2 * WSEG, b1, nullptr, nullptr, nullptr, hh, MROWS, D4, DD, 1);
    // 7) t2 = h @ w2 + b2 + l1h (fp16 residual) -> fp32  [256 tiles]
    hmma_gemm_kernel<<<256, 256, HMMA_SMEM>>>(
        hh, wh + 6 * WSEG, b2, nullptr, l1h, t2, nullptr, MROWS, DD, D4, 0);
    // 8) out = LN(t2)
    ln_kernel<<<MROWS / 8, 256>>>(t2, ln2_g, ln2_b, out, nullptr);
}

// round 15
// speedup vs baseline: 1.0170x; 1.0170x over previous
#include <cuda_runtime.h>
#include <cuda_fp16.h>
#include <cstdint>
#include <cstddef>

// Problem constants
#define BB 2
#define SS 2048
#define DD 1024
#define HH 16
#define DH 64
#define MROWS (BB*SS)          // 4096
#define D4 (4*DD)              // 4096
#define WSEG 1048576           // 1M elements per D*D weight

// ---------------- scratch (device globals; no allocations) ----------------
__device__ __half g_wh [10*WSEG];     // wq | fc | w1 | w2 (fp16)
__device__ __half g_xh [MROWS*DD];    // x fp16
__device__ __half g_qh [MROWS*DD];    // q projection fp16
__device__ __half g_ah [MROWS*DD];    // attention out fp16
__device__ __half g_t1h[MROWS*DD];    // pre-LN1 fp16
__device__ __half g_l1h[MROWS*DD];    // ln1 fp16
__device__ __half g_hh [MROWS*D4];    // mlp hidden fp16 (relu'd)
__device__ float  g_t2 [MROWS*DD];

// ================= helpers =================
__device__ __forceinline__ uint32_t smem_u32(const void* p) {
    uint32_t a;
    asm("{ .reg .u64 t; cvta.to.shared.u64 t, %1; cvt.u32.u64 %0, t; }" : "=r"(a) : "l"(p));
    return a;
}
__device__ __forceinline__ float ex2(float x) {
    float y; asm("ex2.approx.ftz.f32 %0, %1;" : "=f"(y) : "f"(x)); return y;
}
__device__ __forceinline__ uint32_t cvth2(float x, float y) {
    uint32_t h;
    asm("cvt.rn.f16x2.f32 %0, %1, %2;" : "=r"(h) : "f"(y), "f"(x));
    return h;
}
__device__ __forceinline__ void ldsm4(uint32_t* r, uint32_t addr) {
    asm volatile("ldmatrix.sync.aligned.m8n8.x4.shared.b16 {%0,%1,%2,%3}, [%4];"
                 : "=r"(r[0]), "=r"(r[1]), "=r"(r[2]), "=r"(r[3]) : "r"(addr));
}
__device__ __forceinline__ void ldsm4t(uint32_t* r, uint32_t addr) {
    asm volatile("ldmatrix.sync.aligned.m8n8.x4.trans.shared.b16 {%0,%1,%2,%3}, [%4];"
                 : "=r"(r[0]), "=r"(r[1]), "=r"(r[2]), "=r"(r[3]) : "r"(addr));
}
__device__ __forceinline__ void mma16816(float* d, const uint32_t* a, uint32_t b0, uint32_t b1) {
    asm volatile(
        "mma.sync.aligned.m16n8k16.row.col.f32.f16.f16.f32 "
        "{%0,%1,%2,%3}, {%4,%5,%6,%7}, {%8,%9}, {%0,%1,%2,%3};"
        : "+f"(d[0]), "+f"(d[1]), "+f"(d[2]), "+f"(d[3])
        : "r"(a[0]), "r"(a[1]), "r"(a[2]), "r"(a[3]), "r"(b0), "r"(b1));
}
__device__ __forceinline__ void cp16(uint32_t dst, const void* src) {
    asm volatile("cp.async.cg.shared.global [%0], [%1], 16;" :: "r"(dst), "l"(src) : "memory");
}
#define CP_COMMIT() asm volatile("cp.async.commit_group;" ::: "memory")
#define CP_WAIT0()  asm volatile("cp.async.wait_group 0;" ::: "memory")
#define CP_WAIT1()  asm volatile("cp.async.wait_group 1;" ::: "memory")
#define CP_WAIT2()  asm volatile("cp.async.wait_group 2;" ::: "memory")

// ================= pack wq_w [H,D,Dh] -> Wq fp16 [D, D] =================
__global__ void pack_wq_kernel(const float* __restrict__ wq_w, __half* __restrict__ Wq) {
    int idx = blockIdx.x * blockDim.x + threadIdx.x;
    if (idx >= DD * DD) return;
    int d = idx / DD;
    int n = idx % DD;
    int h = n / DH;
    int e = n % DH;
    Wq[idx] = __float2half_rn(wq_w[((size_t)h * DD + d) * DH + e]);
}

// ================= fp32 -> fp16 converter =================
__global__ void conv_f16_kernel(const float* __restrict__ src, __half* __restrict__ dst, int n4) {
    int i = blockIdx.x * blockDim.x + threadIdx.x;
    if (i >= n4) return;
    float4 v = ((const float4*)src)[i];
    uint2 o;
    o.x = cvth2(v.x, v.y);
    o.y = cvth2(v.z, v.w);
    ((uint2*)dst)[i] = o;
}

// ================= fp16 HMMA GEMM (256 threads, warp 64x32, K-stage 64, 3-stage) ======
// Residual (fp32 or fp16) may combine with either fp32 or fp16 output.
#define STAGE_BYTES 32768
#define HMMA_SMEM (3 * STAGE_BYTES + 128)

__global__ __launch_bounds__(256, 2) void hmma_gemm_kernel(
    const __half* __restrict__ A, const __half* __restrict__ W,
    const float* __restrict__ bias,
    const float* __restrict__ resid, const __half* __restrict__ residh,
    float* __restrict__ C, __half* __restrict__ Ch,
    int M, int N, int K, int relu)
{
    extern __shared__ char dsm_raw[];
    uint32_t sraw = smem_u32(dsm_raw);
    uint32_t sb = (sraw + 127u) & ~127u;

    const int tid = threadIdx.x;
    const int wid = tid >> 5;
    const int l   = tid & 31;
    const int wm  = wid >> 2;     // 0..1
    const int wn  = wid & 3;      // 0..3
    const int row0 = blockIdx.y * 128;
    const int col0 = blockIdx.x * 128;

    float acc[16][4];
#pragma unroll
    for (int i = 0; i < 16; i++)
#pragma unroll
        for (int j = 0; j < 4; j++) acc[i][j] = 0.f;

    const int NS = K >> 6;   // K-stage 64

    auto cpStage = [&](int s) {
        uint32_t base = sb + (uint32_t)(s % 3) * STAGE_BYTES;
        int k0 = s << 6;
#pragma unroll
        for (int i = 0; i < 4; i++) {
            int idx = tid + i * 256;
            uint32_t r = (uint32_t)idx >> 3, c = (uint32_t)idx & 7;
            uint32_t aoff = r * 128 + ((c ^ (r & 7)) << 4);
            cp16(base + aoff, A + (size_t)(row0 + r) * K + k0 + c * 8);
        }
#pragma unroll
        for (int i = 0; i < 4; i++) {
            int idx = tid + i * 256;
            uint32_t k = (uint32_t)idx >> 4, c = (uint32_t)idx & 15;
            uint32_t boff = k * 256 + ((c ^ (k & 7)) << 4);
            cp16(base + 16384 + boff, W + (size_t)(k0 + k) * N + col0 + c * 8);
        }
        CP_COMMIT();
    };

    const uint32_t l15 = l & 15;
    const uint32_t ack = (uint32_t)(l >> 4);
    const uint32_t bk7 = (uint32_t)(l & 7);
    const uint32_t bka = (uint32_t)(l >> 4) * 8;
    const uint32_t bna = (uint32_t)((l >> 3) & 1) * 8;

    cpStage(0);
    if (NS > 1) cpStage(1);

    for (int s = 0; s < NS; s++) {
        __syncthreads();
        if (s + 2 < NS) { cpStage(s + 2); CP_WAIT2(); }
        else if (s + 1 < NS) { CP_WAIT1(); }
        else { CP_WAIT0(); }
        __syncthreads();

        uint32_t base = sb + (uint32_t)(s % 3) * STAGE_BYTES;
        uint32_t Ab = base, Bb = base + 16384;

#pragma unroll
        for (int kk16 = 0; kk16 < 4; kk16++) {
            uint32_t ah[4][4], bh[2][4];
            uint32_t ac = (uint32_t)(kk16 * 2) + ack;
#pragma unroll
            for (int i = 0; i < 4; i++) {
                uint32_t row = wm * 64 + i * 16 + l15;
                uint32_t ad = row * 128 + ((ac ^ (row & 7)) << 4);
                ldsm4(ah[i], Ab + ad);
            }
#pragma unroll
            for (int j2 = 0; j2 < 2; j2++) {
                uint32_t krow = (uint32_t)(kk16 * 16) + bka + bk7;
                uint32_t ncol = wn * 32 + j2 * 16 + bna;
                uint32_t bd = krow * 256 + (((ncol >> 3) ^ bk7) << 4);
                ldsm4t(bh[j2], Bb + bd);
            }
#pragma unroll
            for (int i = 0; i < 4; i++) {
#pragma unroll
                for (int j = 0; j < 4; j++) {
                    int j2 = j >> 1, jj = j & 1;
                    mma16816(acc[i * 4 + j], ah[i], bh[j2][jj], bh[j2][2 + jj]);
                }
            }
        }
    }

    // ---- epilogue ----
    const int tq = l >> 2;
    const int tr = (l & 3) * 2;
#pragma unroll
    for (int j = 0; j < 4; j++) {
        int c = col0 + wn * 32 + j * 8 + tr;
        float bx = 0.f, by = 0.f;
        if (bias) { bx = bias[c]; by = bias[c + 1]; }
#pragma unroll
        for (int i = 0; i < 4; i++) {
            int m0 = row0 + wm * 64 + i * 16 + tq;
            float* d = acc[i * 4 + j];
            float v0x = d[0] + bx, v0y = d[1] + by;
            float v1x = d[2] + bx, v1y = d[3] + by;
            if (resid) {
                float2 r0 = *(const float2*)(resid + (size_t)m0 * N + c);
                float2 r1 = *(const float2*)(resid + (size_t)(m0 + 8) * N + c);
                v0x += r0.x; v0y += r0.y; v1x += r1.x; v1y += r1.y;
            } else if (residh) {
                float2 r0 = __half22float2(*(const __half2*)(residh + (size_t)m0 * N + c));
                float2 r1 = __half22float2(*(const __half2*)(residh + (size_t)(m0 + 8) * N + c));
                v0x += r0.x; v0y += r0.y; v1x += r1.x; v1y += r1.y;
            }
            if (relu) {
                v0x = fmaxf(v0x, 0.f); v0y = fmaxf(v0y, 0.f);
                v1x = fmaxf(v1x, 0.f); v1y = fmaxf(v1y, 0.f);
            }
            if (Ch) {
                *(uint32_t*)((uint16_t*)Ch + (size_t)m0 * N + c) = cvth2(v0x, v0y);
                *(uint32_t*)((uint16_t*)Ch + (size_t)(m0 + 8) * N + c) = cvth2(v1x, v1y);
            } else {
                *(float2*)(C + (size_t)m0 * N + c) = make_float2(v0x, v0y);
                *(float2*)(C + (size_t)(m0 + 8) * N + c) = make_float2(v1x, v1y);
            }
        }
    }
}

// ================= flash attention, fp16 HMMA (Q=K=V), q-tile 64 (R11 config) =========
#define FLASH_SMEM (40 * 1024 + 128)
#define SCALE2 0.18033688011112042f   /* log2(e)/8 */

__global__ __launch_bounds__(128, 3) void flash_hmma_kernel(
    const __half* __restrict__ qh, __half* __restrict__ oh)
{
    extern __shared__ char dsm_raw[];
    uint32_t sraw = smem_u32(dsm_raw);
    uint32_t sb = (sraw + 127u) & ~127u;

    const int tid = threadIdx.x;
    const int w   = tid >> 5;
    const int l   = tid & 31;
    const int q0  = blockIdx.x * 64;
    const int h   = blockIdx.y;
    const int b   = blockIdx.z;

    const uint32_t Qb = sb;
    const size_t gbase = (size_t)b * SS * DD + h * DH;

    {
#pragma unroll
        for (int i = 0; i < 4; i++) {
            int idx = tid + i * 128;
            uint32_t r = idx >> 3, c = idx & 7;
            uint32_t off = r * 128 + ((c ^ (r & 7)) << 4);
            cp16(Qb + off, qh + gbase + (size_t)(q0 + r) * DD + c * 8);
        }
#pragma unroll
        for (int i = 0; i < 8; i++) {
            int idx = tid + i * 128;
            uint32_t r = idx >> 3, c = idx & 7;
            uint32_t off = r * 128 + ((c ^ (r & 7)) << 4);
            cp16(sb + 8192 + off, qh + gbase + (size_t)r * DD + c * 8);
        }
        CP_COMMIT();
    }

    uint32_t aq[4][4];
    float S[16][4];
    float O[8][4];
    float m0 = -1e30f, m1 = -1e30f, l0 = 0.f, l1 = 0.f;
#pragma unroll
    for (int i = 0; i < 8; i++)
#pragma unroll
        for (int j = 0; j < 4; j++) O[i][j] = 0.f;

    const uint32_t l15 = l & 15;
    const uint32_t keyoff = (uint32_t)((l & 7) + ((l >> 3) & 1) * 8);
    const uint32_t kcadd  = (uint32_t)(l >> 4);
    const uint32_t vk7    = (uint32_t)(l & 7);
    const uint32_t vka    = (uint32_t)(l >> 4) * 8;
    const uint32_t vna    = (uint32_t)((l >> 3) & 1);

    const int NT = SS / 128;
    for (int kt = 0; kt < NT; kt++) {
        int p = kt & 1;
        __syncthreads();
        if (kt + 1 < NT) {
            uint32_t Kd = sb + 8192 + (uint32_t)(p ^ 1) * 16384u;
#pragma unroll
            for (int i = 0; i < 8; i++) {
                int idx = tid + i * 128;
                uint32_t r = idx >> 3, c = idx & 7;
                uint32_t off = r * 128 + ((c ^ (r & 7)) << 4);
                cp16(Kd + off, qh + gbase + (size_t)((kt + 1) * 128 + r) * DD + c * 8);
            }
            CP_COMMIT();
            CP_WAIT1();
        } else {
            CP_WAIT0();
        }
        __syncthreads();

        if (kt == 0) {
#pragma unroll
            for (int ks = 0; ks < 4; ks++) {
                uint32_t row = (uint32_t)(w * 16) + l15;
                uint32_t ch = (uint32_t)(ks * 2) + kcadd;
                uint32_t ad = row * 128 + ((ch ^ (row & 7)) << 4);
                ldsm4(aq[ks], Qb + ad);
            }
        }

        uint32_t Kb = sb + 8192 + (uint32_t)p * 16384u;

        // ---- S = Q @ K^T ----
#pragma unroll
        for (int nt = 0; nt < 16; nt++)
#pragma unroll
            for (int c = 0; c < 4; c++) S[nt][c] = 0.f;
#pragma unroll
        for (int ks = 0; ks < 4; ks++) {
#pragma unroll
            for (int nb = 0; nb < 8; nb++) {
                uint32_t key = (uint32_t)(nb * 16) + keyoff;
                uint32_t ch = (uint32_t)(ks * 2) + kcadd;
                uint32_t ad = key * 128 + ((ch ^ (key & 7)) << 4);
                uint32_t bh[4];
                ldsm4(bh, Kb + ad);
#pragma unroll
                for (int jj = 0; jj < 2; jj++)
                    mma16816(S[nb * 2 + jj], aq[ks], bh[jj], bh[2 + jj]);
            }
        }

        // ---- online softmax ----
        float mx0 = -1e30f, mx1 = -1e30f;
#pragma unroll
        for (int nt = 0; nt < 16; nt++) {
            mx0 = fmaxf(mx0, fmaxf(S[nt][0], S[nt][1]));
            mx1 = fmaxf(mx1, fmaxf(S[nt][2], S[nt][3]));
        }
        mx0 = fmaxf(mx0, __shfl_xor_sync(0xffffffffu, mx0, 1));
        mx0 = fmaxf(mx0, __shfl_xor_sync(0xffffffffu, mx0, 2));
        mx1 = fmaxf(mx1, __shfl_xor_sync(0xffffffffu, mx1, 1));
        mx1 = fmaxf(mx1, __shfl_xor_sync(0xffffffffu, mx1, 2));
        float mn0 = fmaxf(m0, mx0), mn1 = fmaxf(m1, mx1);
        float s0 = 0.f, s1 = 0.f;
#pragma unroll
        for (int nt = 0; nt < 16; nt++) {
            S[nt][0] = ex2((S[nt][0] - mn0) * SCALE2);
            S[nt][1] = ex2((S[nt][1] - mn0) * SCALE2);
            S[nt][2] = ex2((S[nt][2] - mn1) * SCALE2);
            S[nt][3] = ex2((S[nt][3] - mn1) * SCALE2);
            s0 += S[nt][0] + S[nt][1];
            s1 += S[nt][2] + S[nt][3];
        }
        s0 += __shfl_xor_sync(0xffffffffu, s0, 1);
        s0 += __shfl_xor_sync(0xffffffffu, s0, 2);
        s1 += __shfl_xor_sync(0xffffffffu, s1, 1);
        s1 += __shfl_xor_sync(0xffffffffu, s1, 2);
        float a0 = ex2((m0 - mn0) * SCALE2);
        float a1 = ex2((m1 - mn1) * SCALE2);
        l0 = l0 * a0 + s0;
        l1 = l1 * a1 + s1;
        m0 = mn0; m1 = mn1;
#pragma unroll
        for (int nt = 0; nt < 8; nt++) {
            O[nt][0] *= a0; O[nt][1] *= a0;
            O[nt][2] *= a1; O[nt][3] *= a1;
        }

        // ---- O += P @ V ----
#pragma unroll
        for (int kp = 0; kp < 8; kp++) {
            uint32_t ph[4];
            ph[0] = cvth2(S[2 * kp][0],     S[2 * kp][1]);
            ph[1] = cvth2(S[2 * kp][2],     S[2 * kp][3]);
            ph[2] = cvth2(S[2 * kp + 1][0], S[2 * kp + 1][1]);
            ph[3] = cvth2(S[2 * kp + 1][2], S[2 * kp + 1][3]);
#pragma unroll
            for (int j2 = 0; j2 < 4; j2++) {
                uint32_t krow = (uint32_t)(kp * 16) + vka + vk7;
                uint32_t chn = (uint32_t)(j2 * 2) + vna;
                uint32_t ad = krow * 128 + ((chn ^ (krow & 7)) << 4);
                uint32_t vh[4];
                ldsm4t(vh, Kb + ad);
#pragma unroll
                for (int jj = 0; jj < 2; jj++)
                    mma16816(O[j2 * 2 + jj], ph, vh[jj], vh[2 + jj]);
            }
        }
    }

    // ---- write normalized output as fp16 ----
    float inv0 = 1.0f / l0, inv1 = 1.0f / l1;
    int r0 = l >> 2;
    int fb = (l & 3) * 2;
    uint16_t* op = (uint16_t*)oh + gbase + (size_t)(q0 + w * 16) * DD;
#pragma unroll
    for (int nt = 0; nt < 8; nt++) {
        int f = nt * 8 + fb;
        *(uint32_t*)(op + (size_t)r0 * DD + f) = cvth2(O[nt][0] * inv0, O[nt][1] * inv0);
        *(uint32_t*)(op + (size_t)(r0 + 8) * DD + f) = cvth2(O[nt][2] * inv1, O[nt][3] * inv1);
    }
}

// ================= layernorm (fp32 in): warp-per-row =================
__global__ __launch_bounds__(256) void ln_kernel(
    const float* __restrict__ in, const float* __restrict__ gw,
    const float* __restrict__ bw, float* __restrict__ out,
    __half* __restrict__ oh)
{
    const int warp = threadIdx.x >> 5;
    const int lane = threadIdx.x & 31;
    const int row = blockIdx.x * 8 + warp;

    const float4* p = (const float4*)(in + (size_t)row * DD);
    float4 v[8];
#pragma unroll
    for (int i = 0; i < 8; i++) v[i] = p[lane + i * 32];

    float s = 0.f, sq = 0.f;
#pragma unroll
    for (int i = 0; i < 8; i++) {
        s  += v[i].x + v[i].y + v[i].z + v[i].w;
        sq += v[i].x * v[i].x + v[i].y * v[i].y + v[i].z * v[i].z + v[i].w * v[i].w;
    }
#pragma unroll
    for (int off = 16; off > 0; off >>= 1) {
        s  += __shfl_xor_sync(0xffffffffu, s,  off);
        sq += __shfl_xor_sync(0xffffffffu, sq, off);
    }
    const float mu  = s * (1.0f / DD);
    const float var = sq * (1.0f / DD) - mu * mu;
    const float r   = rsqrtf(var + 1e-5f);

    float4* po = out ? (float4*)(out + (size_t)row * DD) : nullptr;
    uint2* ph = oh ? (uint2*)oh + (size_t)row * (DD / 4) : nullptr;
#pragma unroll
    for (int i = 0; i < 8; i++) {
        int c = lane + i * 32;
        const float4 g4 = ((const float4*)gw)[c];
        const float4 b4 = ((const float4*)bw)[c];
        float4 ov;
        ov.x = (v[i].x - mu) * r * g4.x + b4.x;
        ov.y = (v[i].y - mu) * r * g4.y + b4.y;
        ov.z = (v[i].z - mu) * r * g4.z + b4.z;
        ov.w = (v[i].w - mu) * r * g4.w + b4.w;
        if (po) po[c] = ov;
        if (ph) {
            uint2 o;
            o.x = cvth2(ov.x, ov.y);
            o.y = cvth2(ov.z, ov.w);
            ph[c] = o;
        }
    }
}

// ================= layernorm (fp16 in -> fp16 out): warp-per-row =================
__global__ __launch_bounds__(256) void ln_h_kernel(
    const __half* __restrict__ in, const float* __restrict__ gw,
    const float* __restrict__ bw, __half* __restrict__ oh)
{
    const int warp = threadIdx.x >> 5;
    const int lane = threadIdx.x & 31;
    const int row = blockIdx.x * 8 + warp;

    const uint2* p = (const uint2*)in + (size_t)row * (DD / 4);
    float4 v[8];
#pragma unroll
    for (int i = 0; i < 8; i++) {
        uint2 u = p[lane + i * 32];
        float2 lo = __half22float2(*(__half2*)&u.x);
        float2 hi = __half22float2(*(__half2*)&u.y);
        v[i] = make_float4(lo.x, lo.y, hi.x, hi.y);
    }

    float s = 0.f, sq = 0.f;
#pragma unroll
    for (int i = 0; i < 8; i++) {
        s  += v[i].x + v[i].y + v[i].z + v[i].w;
        sq += v[i].x * v[i].x + v[i].y * v[i].y + v[i].z * v[i].z + v[i].w * v[i].w;
    }
#pragma unroll
    for (int off = 16; off > 0; off >>= 1) {
        s  += __shfl_xor_sync(0xffffffffu, s,  off);
        sq += __shfl_xor_sync(0xffffffffu, sq, off);
    }
    const float mu  = s * (1.0f / DD);
    const float var = sq * (1.0f / DD) - mu * mu;
    const float r   = rsqrtf(var + 1e-5f);

    uint2* ph = (uint2*)oh + (size_t)row * (DD / 4);
#pragma unroll
    for (int i = 0; i < 8; i++) {
        int c = lane + i * 32;
        const float4 g4 = ((const float4*)gw)[c];
        const float4 b4 = ((const float4*)bw)[c];
        uint2 o;
        o.x = cvth2((v[i].x - mu) * r * g4.x + b4.x, (v[i].y - mu) * r * g4.y + b4.y);
        o.y = cvth2((v[i].z - mu) * r * g4.z + b4.z, (v[i].w - mu) * r * g4.w + b4.w);
        ph[c] = o;
    }
}

// ================= launch =================
extern "C" void kernel_launch(void* const* d_in, const int* in_sizes, int n_in,
                              void* d_out, int out_size)
{
    const float* x     = (const float*)d_in[0];
    const float* wq_w  = (const float*)d_in[1];
    const float* wq_b  = (const float*)d_in[2];
    const float* fc_w  = (const float*)d_in[3];
    const float* fc_b  = (const float*)d_in[4];
    const float* ln1_g = (const float*)d_in[5];
    const float* ln1_b = (const float*)d_in[6];
    const float* w1    = (const float*)d_in[7];
    const float* b1    = (const float*)d_in[8];
    const float* w2    = (const float*)d_in[9];
    const float* b2    = (const float*)d_in[10];
    const float* ln2_g = (const float*)d_in[11];
    const float* ln2_b = (const float*)d_in[12];
    float* out = (float*)d_out;

    float *t2;
    __half *wh, *xh, *qh, *ah, *t1h, *l1h, *hh;
    cudaGetSymbolAddress((void**)&wh,  g_wh);
    cudaGetSymbolAddress((void**)&xh,  g_xh);
    cudaGetSymbolAddress((void**)&qh,  g_qh);
    cudaGetSymbolAddress((void**)&ah,  g_ah);
    cudaGetSymbolAddress((void**)&t1h, g_t1h);
    cudaGetSymbolAddress((void**)&l1h, g_l1h);
    cudaGetSymbolAddress((void**)&hh,  g_hh);
    cudaGetSymbolAddress((void**)&t2,  g_t2);

    cudaFuncSetAttribute(hmma_gemm_kernel, cudaFuncAttributeMaxDynamicSharedMemorySize, HMMA_SMEM);
    cudaFuncSetAttribute(flash_hmma_kernel, cudaFuncAttributeMaxDynamicSharedMemorySize, FLASH_SMEM);

    // 1) pack Wq (fp16); convert weights + x to fp16
    pack_wq_kernel<<<(DD * DD + 255) / 256, 256>>>(wq_w, wh);
    conv_f16_kernel<<<(WSEG / 4 + 255) / 256, 256>>>(fc_w, wh + WSEG, WSEG / 4);
    conv_f16_kernel<<<(WSEG + 255) / 256, 256>>>(w1, wh + 2 * WSEG, WSEG);
    conv_f16_kernel<<<(WSEG + 255) / 256, 256>>>(w2, wh + 6 * WSEG, WSEG);
    conv_f16_kernel<<<(MROWS * DD / 4 + 255) / 256, 256>>>(x, xh, MROWS * DD / 4);

    // 2) qh = x @ Wq + wq_b  (fp16 out)
    hmma_gemm_kernel<<<dim3(DD / 128, MROWS / 128), 256, HMMA_SMEM>>>(
        xh, wh, wq_b, nullptr, nullptr, nullptr, qh, MROWS, DD, DD, 0);
    // 3) flash attention (fp16 out), q-tile 64, 3 CTA/SM
    flash_hmma_kernel<<<dim3(SS / 64, HH, BB), 128, FLASH_SMEM>>>(qh, ah);
    // 4) t1h = attn @ fc_w + fc_b + xh  (fp16 out, fp16 residual)
    hmma_gemm_kernel<<<dim3(DD / 128, MROWS / 128), 256, HMMA_SMEM>>>(
        ah, wh + WSEG, fc_b, nullptr, xh, nullptr, t1h, MROWS, DD, DD, 0);
    // 5) l1h = LN(t1h)  (fp16 in/out)
    ln_h_kernel<<<MROWS / 8, 256>>>(t1h, ln1_g, ln1_b, l1h);
    // 6) h = relu(l1h @ w1 + b1) (fp16 out)
    hmma_gemm_kernel<<<dim3(D4 / 128, MROWS / 128), 256, HMMA_SMEM>>>(
        l1h, wh + 2 * WSEG, b1, nullptr, nullptr, nullptr, hh, MROWS, D4, DD, 1);
    // 7) t2 = h @ w2 + b2 + l1h (fp16 residual) -> fp32
    hmma_gemm_kernel<<<dim3(DD / 128, MROWS / 128), 256, HMMA_SMEM>>>(
        hh, wh + 6 * WSEG, b2, nullptr, l1h, t2, nullptr, MROWS, DD, D4, 0);
    // 8) out = LN(t2)
    ln_kernel<<<MROWS / 8, 256>>>(t2, ln2_g, ln2_b, out, nullptr);
}

// round 16
// speedup vs baseline: 1.0432x; 1.0257x over previous
#include <cuda_runtime.h>
#include <cuda_fp16.h>
#include <cstdint>
#include <cstddef>

// Problem constants
#define BB 2
#define SS 2048
#define DD 1024
#define HH 16
#define DH 64
#define MROWS (BB*SS)          // 4096
#define D4 (4*DD)              // 4096
#define WSEG 1048576           // 1M elements per D*D weight

// ---------------- scratch (device globals; no allocations) ----------------
__device__ __half g_wh [10*WSEG];     // wq | fc | w1 | w2 (fp16)
__device__ __half g_xh [MROWS*DD];    // x fp16
__device__ __half g_qh [MROWS*DD];    // q projection fp16
__device__ __half g_ah [MROWS*DD];    // attention out fp16
__device__ __half g_t1h[MROWS*DD];    // pre-LN1 fp16
__device__ __half g_l1h[MROWS*DD];    // ln1 fp16
__device__ __half g_hh [MROWS*D4];    // mlp hidden fp16 (relu'd)
__device__ __half g_t2h[MROWS*DD];    // pre-LN2 fp16

// ================= helpers =================
__device__ __forceinline__ uint32_t smem_u32(const void* p) {
    uint32_t a;
    asm("{ .reg .u64 t; cvta.to.shared.u64 t, %1; cvt.u32.u64 %0, t; }" : "=r"(a) : "l"(p));
    return a;
}
__device__ __forceinline__ float ex2(float x) {
    float y; asm("ex2.approx.ftz.f32 %0, %1;" : "=f"(y) : "f"(x)); return y;
}
__device__ __forceinline__ uint32_t cvth2(float x, float y) {
    uint32_t h;
    asm("cvt.rn.f16x2.f32 %0, %1, %2;" : "=r"(h) : "f"(y), "f"(x));
    return h;
}
__device__ __forceinline__ void ldsm4(uint32_t* r, uint32_t addr) {
    asm volatile("ldmatrix.sync.aligned.m8n8.x4.shared.b16 {%0,%1,%2,%3}, [%4];"
                 : "=r"(r[0]), "=r"(r[1]), "=r"(r[2]), "=r"(r[3]) : "r"(addr));
}
__device__ __forceinline__ void ldsm4t(uint32_t* r, uint32_t addr) {
    asm volatile("ldmatrix.sync.aligned.m8n8.x4.trans.shared.b16 {%0,%1,%2,%3}, [%4];"
                 : "=r"(r[0]), "=r"(r[1]), "=r"(r[2]), "=r"(r[3]) : "r"(addr));
}
__device__ __forceinline__ void mma16816(float* d, const uint32_t* a, uint32_t b0, uint32_t b1) {
    asm volatile(
        "mma.sync.aligned.m16n8k16.row.col.f32.f16.f16.f32 "
        "{%0,%1,%2,%3}, {%4,%5,%6,%7}, {%8,%9}, {%0,%1,%2,%3};"
        : "+f"(d[0]), "+f"(d[1]), "+f"(d[2]), "+f"(d[3])
        : "r"(a[0]), "r"(a[1]), "r"(a[2]), "r"(a[3]), "r"(b0), "r"(b1));
}
__device__ __forceinline__ void cp16(uint32_t dst, const void* src) {
    asm volatile("cp.async.cg.shared.global [%0], [%1], 16;" :: "r"(dst), "l"(src) : "memory");
}
#define CP_COMMIT() asm volatile("cp.async.commit_group;" ::: "memory")
#define CP_WAIT0()  asm volatile("cp.async.wait_group 0;" ::: "memory")
#define CP_WAIT1()  asm volatile("cp.async.wait_group 1;" ::: "memory")
#define CP_WAIT2()  asm volatile("cp.async.wait_group 2;" ::: "memory")

// ================= pack wq_w [H,D,Dh] -> Wq fp16 [D, D] =================
__global__ void pack_wq_kernel(const float* __restrict__ wq_w, __half* __restrict__ Wq) {
    int idx = blockIdx.x * blockDim.x + threadIdx.x;
    if (idx >= DD * DD) return;
    int d = idx / DD;
    int n = idx % DD;
    int h = n / DH;
    int e = n % DH;
    Wq[idx] = __float2half_rn(wq_w[((size_t)h * DD + d) * DH + e]);
}

// ================= merged fp32 -> fp16 converter (fc_w | w1 | w2 | x) =================
#define N_FC (WSEG / 4)
#define N_W  (WSEG)
#define N_X  (MROWS * DD / 4)
#define N_CONV_TOTAL (N_FC + 2 * N_W + N_X)

__global__ void conv_all_kernel(const float* __restrict__ fc_w,
                                const float* __restrict__ w1,
                                const float* __restrict__ w2,
                                const float* __restrict__ x,
                                __half* __restrict__ wh,
                                __half* __restrict__ xh) {
    int i = blockIdx.x * blockDim.x + threadIdx.x;
    if (i >= N_CONV_TOTAL) return;
    const float* src;
    __half* dst;
    int j;
    if (i < N_FC)                  { src = fc_w; dst = wh + WSEG;     j = i; }
    else if (i < N_FC + N_W)       { src = w1;   dst = wh + 2 * WSEG; j = i - N_FC; }
    else if (i < N_FC + 2 * N_W)   { src = w2;   dst = wh + 6 * WSEG; j = i - N_FC - N_W; }
    else                           { src = x;    dst = xh;            j = i - N_FC - 2 * N_W; }
    float4 v = ((const float4*)src)[j];
    uint2 o;
    o.x = cvth2(v.x, v.y);
    o.y = cvth2(v.z, v.w);
    ((uint2*)dst)[j] = o;
}

// ================= fp16 HMMA GEMM (256 threads, warp 64x32, K-stage 64, 3-stage) ======
#define STAGE_BYTES 32768
#define HMMA_SMEM (3 * STAGE_BYTES + 128)

__global__ __launch_bounds__(256, 2) void hmma_gemm_kernel(
    const __half* __restrict__ A, const __half* __restrict__ W,
    const float* __restrict__ bias,
    const __half* __restrict__ residh,
    float* __restrict__ C, __half* __restrict__ Ch,
    int M, int N, int K, int relu)
{
    extern __shared__ char dsm_raw[];
    uint32_t sraw = smem_u32(dsm_raw);
    uint32_t sb = (sraw + 127u) & ~127u;

    const int tid = threadIdx.x;
    const int wid = tid >> 5;
    const int l   = tid & 31;
    const int wm  = wid >> 2;     // 0..1
    const int wn  = wid & 3;      // 0..3
    const int row0 = blockIdx.y * 128;
    const int col0 = blockIdx.x * 128;

    float acc[16][4];
#pragma unroll
    for (int i = 0; i < 16; i++)
#pragma unroll
        for (int j = 0; j < 4; j++) acc[i][j] = 0.f;

    const int NS = K >> 6;   // K-stage 64

    auto cpStage = [&](int s) {
        uint32_t base = sb + (uint32_t)(s % 3) * STAGE_BYTES;
        int k0 = s << 6;
#pragma unroll
        for (int i = 0; i < 4; i++) {
            int idx = tid + i * 256;
            uint32_t r = (uint32_t)idx >> 3, c = (uint32_t)idx & 7;
            uint32_t aoff = r * 128 + ((c ^ (r & 7)) << 4);
            cp16(base + aoff, A + (size_t)(row0 + r) * K + k0 + c * 8);
        }
#pragma unroll
        for (int i = 0; i < 4; i++) {
            int idx = tid + i * 256;
            uint32_t k = (uint32_t)idx >> 4, c = (uint32_t)idx & 15;
            uint32_t boff = k * 256 + ((c ^ (k & 7)) << 4);
            cp16(base + 16384 + boff, W + (size_t)(k0 + k) * N + col0 + c * 8);
        }
        CP_COMMIT();
    };

    const uint32_t l15 = l & 15;
    const uint32_t ack = (uint32_t)(l >> 4);
    const uint32_t bk7 = (uint32_t)(l & 7);
    const uint32_t bka = (uint32_t)(l >> 4) * 8;
    const uint32_t bna = (uint32_t)((l >> 3) & 1) * 8;

    cpStage(0);
    if (NS > 1) cpStage(1);

    for (int s = 0; s < NS; s++) {
        __syncthreads();
        if (s + 2 < NS) { cpStage(s + 2); CP_WAIT2(); }
        else if (s + 1 < NS) { CP_WAIT1(); }
        else { CP_WAIT0(); }
        __syncthreads();

        uint32_t base = sb + (uint32_t)(s % 3) * STAGE_BYTES;
        uint32_t Ab = base, Bb = base + 16384;

#pragma unroll
        for (int kk16 = 0; kk16 < 4; kk16++) {
            uint32_t ah[4][4], bh[2][4];
            uint32_t ac = (uint32_t)(kk16 * 2) + ack;
#pragma unroll
            for (int i = 0; i < 4; i++) {
                uint32_t row = wm * 64 + i * 16 + l15;
                uint32_t ad = row * 128 + ((ac ^ (row & 7)) << 4);
                ldsm4(ah[i], Ab + ad);
            }
#pragma unroll
            for (int j2 = 0; j2 < 2; j2++) {
                uint32_t krow = (uint32_t)(kk16 * 16) + bka + bk7;
                uint32_t ncol = wn * 32 + j2 * 16 + bna;
                uint32_t bd = krow * 256 + (((ncol >> 3) ^ bk7) << 4);
                ldsm4t(bh[j2], Bb + bd);
            }
#pragma unroll
            for (int i = 0; i < 4; i++) {
#pragma unroll
                for (int j = 0; j < 4; j++) {
                    int j2 = j >> 1, jj = j & 1;
                    mma16816(acc[i * 4 + j], ah[i], bh[j2][jj], bh[j2][2 + jj]);
                }
            }
        }
    }

    // ---- epilogue ----
    const int tq = l >> 2;
    const int tr = (l & 3) * 2;
#pragma unroll
    for (int j = 0; j < 4; j++) {
        int c = col0 + wn * 32 + j * 8 + tr;
        float bx = 0.f, by = 0.f;
        if (bias) { bx = bias[c]; by = bias[c + 1]; }
#pragma unroll
        for (int i = 0; i < 4; i++) {
            int m0 = row0 + wm * 64 + i * 16 + tq;
            float* d = acc[i * 4 + j];
            float v0x = d[0] + bx, v0y = d[1] + by;
            float v1x = d[2] + bx, v1y = d[3] + by;
            if (residh) {
                float2 r0 = __half22float2(*(const __half2*)(residh + (size_t)m0 * N + c));
                float2 r1 = __half22float2(*(const __half2*)(residh + (size_t)(m0 + 8) * N + c));
                v0x += r0.x; v0y += r0.y; v1x += r1.x; v1y += r1.y;
            }
            if (relu) {
                v0x = fmaxf(v0x, 0.f); v0y = fmaxf(v0y, 0.f);
                v1x = fmaxf(v1x, 0.f); v1y = fmaxf(v1y, 0.f);
            }
            if (Ch) {
                *(uint32_t*)((uint16_t*)Ch + (size_t)m0 * N + c) = cvth2(v0x, v0y);
                *(uint32_t*)((uint16_t*)Ch + (size_t)(m0 + 8) * N + c) = cvth2(v1x, v1y);
            } else {
                *(float2*)(C + (size_t)m0 * N + c) = make_float2(v0x, v0y);
                *(float2*)(C + (size_t)(m0 + 8) * N + c) = make_float2(v1x, v1y);
            }
        }
    }
}

// ================= flash attention, fp16 HMMA (Q=K=V), q-tile 64 (R11 config) =========
#define FLASH_SMEM (40 * 1024 + 128)
#define SCALE2 0.18033688011112042f   /* log2(e)/8 */

__global__ __launch_bounds__(128, 3) void flash_hmma_kernel(
    const __half* __restrict__ qh, __half* __restrict__ oh)
{
    extern __shared__ char dsm_raw[];
    uint32_t sraw = smem_u32(dsm_raw);
    uint32_t sb = (sraw + 127u) & ~127u;

    const int tid = threadIdx.x;
    const int w   = tid >> 5;
    const int l   = tid & 31;
    const int q0  = blockIdx.x * 64;
    const int h   = blockIdx.y;
    const int b   = blockIdx.z;

    const uint32_t Qb = sb;
    const size_t gbase = (size_t)b * SS * DD + h * DH;

    {
#pragma unroll
        for (int i = 0; i < 4; i++) {
            int idx = tid + i * 128;
            uint32_t r = idx >> 3, c = idx & 7;
            uint32_t off = r * 128 + ((c ^ (r & 7)) << 4);
            cp16(Qb + off, qh + gbase + (size_t)(q0 + r) * DD + c * 8);
        }
#pragma unroll
        for (int i = 0; i < 8; i++) {
            int idx = tid + i * 128;
            uint32_t r = idx >> 3, c = idx & 7;
            uint32_t off = r * 128 + ((c ^ (r & 7)) << 4);
            cp16(sb + 8192 + off, qh + gbase + (size_t)r * DD + c * 8);
        }
        CP_COMMIT();
    }

    uint32_t aq[4][4];
    float S[16][4];
    float O[8][4];
    float m0 = -1e30f, m1 = -1e30f, l0 = 0.f, l1 = 0.f;
#pragma unroll
    for (int i = 0; i < 8; i++)
#pragma unroll
        for (int j = 0; j < 4; j++) O[i][j] = 0.f;

    const uint32_t l15 = l & 15;
    const uint32_t keyoff = (uint32_t)((l & 7) + ((l >> 3) & 1) * 8);
    const uint32_t kcadd  = (uint32_t)(l >> 4);
    const uint32_t vk7    = (uint32_t)(l & 7);
    const uint32_t vka    = (uint32_t)(l >> 4) * 8;
    const uint32_t vna    = (uint32_t)((l >> 3) & 1);

    const int NT = SS / 128;
    for (int kt = 0; kt < NT; kt++) {
        int p = kt & 1;
        __syncthreads();
        if (kt + 1 < NT) {
            uint32_t Kd = sb + 8192 + (uint32_t)(p ^ 1) * 16384u;
#pragma unroll
            for (int i = 0; i < 8; i++) {
                int idx = tid + i * 128;
                uint32_t r = idx >> 3, c = idx & 7;
                uint32_t off = r * 128 + ((c ^ (r & 7)) << 4);
                cp16(Kd + off, qh + gbase + (size_t)((kt + 1) * 128 + r) * DD + c * 8);
            }
            CP_COMMIT();
            CP_WAIT1();
        } else {
            CP_WAIT0();
        }
        __syncthreads();

        if (kt == 0) {
#pragma unroll
            for (int ks = 0; ks < 4; ks++) {
                uint32_t row = (uint32_t)(w * 16) + l15;
                uint32_t ch = (uint32_t)(ks * 2) + kcadd;
                uint32_t ad = row * 128 + ((ch ^ (row & 7)) << 4);
                ldsm4(aq[ks], Qb + ad);
            }
        }

        uint32_t Kb = sb + 8192 + (uint32_t)p * 16384u;

        // ---- S = Q @ K^T ----
#pragma unroll
        for (int nt = 0; nt < 16; nt++)
#pragma unroll
            for (int c = 0; c < 4; c++) S[nt][c] = 0.f;
#pragma unroll
        for (int ks = 0; ks < 4; ks++) {
#pragma unroll
            for (int nb = 0; nb < 8; nb++) {
                uint32_t key = (uint32_t)(nb * 16) + keyoff;
                uint32_t ch = (uint32_t)(ks * 2) + kcadd;
                uint32_t ad = key * 128 + ((ch ^ (key & 7)) << 4);
                uint32_t bh[4];
                ldsm4(bh, Kb + ad);
#pragma unroll
                for (int jj = 0; jj < 2; jj++)
                    mma16816(S[nb * 2 + jj], aq[ks], bh[jj], bh[2 + jj]);
            }
        }

        // ---- online softmax ----
        float mx0 = -1e30f, mx1 = -1e30f;
#pragma unroll
        for (int nt = 0; nt < 16; nt++) {
            mx0 = fmaxf(mx0, fmaxf(S[nt][0], S[nt][1]));
            mx1 = fmaxf(mx1, fmaxf(S[nt][2], S[nt][3]));
        }
        mx0 = fmaxf(mx0, __shfl_xor_sync(0xffffffffu, mx0, 1));
        mx0 = fmaxf(mx0, __shfl_xor_sync(0xffffffffu, mx0, 2));
        mx1 = fmaxf(mx1, __shfl_xor_sync(0xffffffffu, mx1, 1));
        mx1 = fmaxf(mx1, __shfl_xor_sync(0xffffffffu, mx1, 2));
        float mn0 = fmaxf(m0, mx0), mn1 = fmaxf(m1, mx1);
        float s0 = 0.f, s1 = 0.f;
#pragma unroll
        for (int nt = 0; nt < 16; nt++) {
            S[nt][0] = ex2((S[nt][0] - mn0) * SCALE2);
            S[nt][1] = ex2((S[nt][1] - mn0) * SCALE2);
            S[nt][2] = ex2((S[nt][2] - mn1) * SCALE2);
            S[nt][3] = ex2((S[nt][3] - mn1) * SCALE2);
            s0 += S[nt][0] + S[nt][1];
            s1 += S[nt][2] + S[nt][3];
        }
        s0 += __shfl_xor_sync(0xffffffffu, s0, 1);
        s0 += __shfl_xor_sync(0xffffffffu, s0, 2);
        s1 += __shfl_xor_sync(0xffffffffu, s1, 1);
        s1 += __shfl_xor_sync(0xffffffffu, s1, 2);
        float a0 = ex2((m0 - mn0) * SCALE2);
        float a1 = ex2((m1 - mn1) * SCALE2);
        l0 = l0 * a0 + s0;
        l1 = l1 * a1 + s1;
        m0 = mn0; m1 = mn1;
#pragma unroll
        for (int nt = 0; nt < 8; nt++) {
            O[nt][0] *= a0; O[nt][1] *= a0;
            O[nt][2] *= a1; O[nt][3] *= a1;
        }

        // ---- O += P @ V ----
#pragma unroll
        for (int kp = 0; kp < 8; kp++) {
            uint32_t ph[4];
            ph[0] = cvth2(S[2 * kp][0],     S[2 * kp][1]);
            ph[1] = cvth2(S[2 * kp][2],     S[2 * kp][3]);
            ph[2] = cvth2(S[2 * kp + 1][0], S[2 * kp + 1][1]);
            ph[3] = cvth2(S[2 * kp + 1][2], S[2 * kp + 1][3]);
#pragma unroll
            for (int j2 = 0; j2 < 4; j2++) {
                uint32_t krow = (uint32_t)(kp * 16) + vka + vk7;
                uint32_t chn = (uint32_t)(j2 * 2) + vna;
                uint32_t ad = krow * 128 + ((chn ^ (krow & 7)) << 4);
                uint32_t vh[4];
                ldsm4t(vh, Kb + ad);
#pragma unroll
                for (int jj = 0; jj < 2; jj++)
                    mma16816(O[j2 * 2 + jj], ph, vh[jj], vh[2 + jj]);
            }
        }
    }

    // ---- write normalized output as fp16 ----
    float inv0 = 1.0f / l0, inv1 = 1.0f / l1;
    int r0 = l >> 2;
    int fb = (l & 3) * 2;
    uint16_t* op = (uint16_t*)oh + gbase + (size_t)(q0 + w * 16) * DD;
#pragma unroll
    for (int nt = 0; nt < 8; nt++) {
        int f = nt * 8 + fb;
        *(uint32_t*)(op + (size_t)r0 * DD + f) = cvth2(O[nt][0] * inv0, O[nt][1] * inv0);
        *(uint32_t*)(op + (size_t)(r0 + 8) * DD + f) = cvth2(O[nt][2] * inv1, O[nt][3] * inv1);
    }
}

// ================= layernorm (fp16 in -> fp32 out and/or fp16 out): warp-per-row ======
__global__ __launch_bounds__(256) void ln_h_kernel(
    const __half* __restrict__ in, const float* __restrict__ gw,
    const float* __restrict__ bw, float* __restrict__ out,
    __half* __restrict__ oh)
{
    const int warp = threadIdx.x >> 5;
    const int lane = threadIdx.x & 31;
    const int row = blockIdx.x * 8 + warp;

    const uint2* p = (const uint2*)in + (size_t)row * (DD / 4);
    float4 v[8];
#pragma unroll
    for (int i = 0; i < 8; i++) {
        uint2 u = p[lane + i * 32];
        float2 lo = __half22float2(*(__half2*)&u.x);
        float2 hi = __half22float2(*(__half2*)&u.y);
        v[i] = make_float4(lo.x, lo.y, hi.x, hi.y);
    }

    float s = 0.f, sq = 0.f;
#pragma unroll
    for (int i = 0; i < 8; i++) {
        s  += v[i].x + v[i].y + v[i].z + v[i].w;
        sq += v[i].x * v[i].x + v[i].y * v[i].y + v[i].z * v[i].z + v[i].w * v[i].w;
    }
#pragma unroll
    for (int off = 16; off > 0; off >>= 1) {
        s  += __shfl_xor_sync(0xffffffffu, s,  off);
        sq += __shfl_xor_sync(0xffffffffu, sq, off);
    }
    const float mu  = s * (1.0f / DD);
    const float var = sq * (1.0f / DD) - mu * mu;
    const float r   = rsqrtf(var + 1e-5f);

    float4* po = out ? (float4*)(out + (size_t)row * DD) : nullptr;
    uint2* ph = oh ? (uint2*)oh + (size_t)row * (DD / 4) : nullptr;
#pragma unroll
    for (int i = 0; i < 8; i++) {
        int c = lane + i * 32;
        const float4 g4 = ((const float4*)gw)[c];
        const float4 b4 = ((const float4*)bw)[c];
        float4 ov;
        ov.x = (v[i].x - mu) * r * g4.x + b4.x;
        ov.y = (v[i].y - mu) * r * g4.y + b4.y;
        ov.z = (v[i].z - mu) * r * g4.z + b4.z;
        ov.w = (v[i].w - mu) * r * g4.w + b4.w;
        if (po) po[c] = ov;
        if (ph) {
            uint2 o;
            o.x = cvth2(ov.x, ov.y);
            o.y = cvth2(ov.z, ov.w);
            ph[c] = o;
        }
    }
}

// ================= launch =================
extern "C" void kernel_launch(void* const* d_in, const int* in_sizes, int n_in,
                              void* d_out, int out_size)
{
    const float* x     = (const float*)d_in[0];
    const float* wq_w  = (const float*)d_in[1];
    const float* wq_b  = (const float*)d_in[2];
    const float* fc_w  = (const float*)d_in[3];
    const float* fc_b  = (const float*)d_in[4];
    const float* ln1_g = (const float*)d_in[5];
    const float* ln1_b = (const float*)d_in[6];
    const float* w1    = (const float*)d_in[7];
    const float* b1    = (const float*)d_in[8];
    const float* w2    = (const float*)d_in[9];
    const float* b2    = (const float*)d_in[10];
    const float* ln2_g = (const float*)d_in[11];
    const float* ln2_b = (const float*)d_in[12];
    float* out = (float*)d_out;

    __half *wh, *xh, *qh, *ah, *t1h, *l1h, *hh, *t2h;
    cudaGetSymbolAddress((void**)&wh,  g_wh);
    cudaGetSymbolAddress((void**)&xh,  g_xh);
    cudaGetSymbolAddress((void**)&qh,  g_qh);
    cudaGetSymbolAddress((void**)&ah,  g_ah);
    cudaGetSymbolAddress((void**)&t1h, g_t1h);
    cudaGetSymbolAddress((void**)&l1h, g_l1h);
    cudaGetSymbolAddress((void**)&hh,  g_hh);
    cudaGetSymbolAddress((void**)&t2h, g_t2h);

    cudaFuncSetAttribute(hmma_gemm_kernel, cudaFuncAttributeMaxDynamicSharedMemorySize, HMMA_SMEM);
    cudaFuncSetAttribute(flash_hmma_kernel, cudaFuncAttributeMaxDynamicSharedMemorySize, FLASH_SMEM);

    // 1) pack Wq (fp16); single merged conversion for fc_w, w1, w2, x
    pack_wq_kernel<<<(DD * DD + 255) / 256, 256>>>(wq_w, wh);
    conv_all_kernel<<<(N_CONV_TOTAL + 255) / 256, 256>>>(fc_w, w1, w2, x, wh, xh);

    // 2) qh = x @ Wq + wq_b  (fp16 out)
    hmma_gemm_kernel<<<dim3(DD / 128, MROWS / 128), 256, HMMA_SMEM>>>(
        xh, wh, wq_b, nullptr, nullptr, qh, MROWS, DD, DD, 0);
    // 3) flash attention (fp16 out), q-tile 64, 3 CTA/SM
    flash_hmma_kernel<<<dim3(SS / 64, HH, BB), 128, FLASH_SMEM>>>(qh, ah);
    // 4) t1h = attn @ fc_w + fc_b + xh  (fp16 out, fp16 residual)
    hmma_gemm_kernel<<<dim3(DD / 128, MROWS / 128), 256, HMMA_SMEM>>>(
        ah, wh + WSEG, fc_b, xh, nullptr, t1h, MROWS, DD, DD, 0);
    // 5) l1h = LN(t1h)  (fp16 in/out)
    ln_h_kernel<<<MROWS / 8, 256>>>(t1h, ln1_g, ln1_b, nullptr, l1h);
    // 6) h = relu(l1h @ w1 + b1) (fp16 out)
    hmma_gemm_kernel<<<dim3(D4 / 128, MROWS / 128), 256, HMMA_SMEM>>>(
        l1h, wh + 2 * WSEG, b1, nullptr, nullptr, hh, MROWS, D4, DD, 1);
    // 7) t2h = h @ w2 + b2 + l1h  (fp16 out, fp16 residual)
    hmma_gemm_kernel<<<dim3(DD / 128, MROWS / 128), 256, HMMA_SMEM>>>(
        hh, wh + 6 * WSEG, b2, l1h, nullptr, t2h, MROWS, DD, D4, 0);
    // 8) out = LN(t2h) -> fp32
    ln_h_kernel<<<MROWS / 8, 256>>>(t2h, ln2_g, ln2_b, out, nullptr);
}